// round 1
// baseline (speedup 1.0000x reference)
#include <cuda_runtime.h>

// 3-layer GRU (PyTorch gate order r,z,n), B=128, T=512, H=512, fp32.
// Persistent wavefront kernel: at tick k, layer l processes timestep t = k - l.
// Double-buffered hidden state (parity = k&1) -> one grid barrier per tick.
// Warp = one hidden unit (1536 units = 128 CTAs x 12 warps); lane holds a
// 16-wide K-slice of all 6 weight rows (3 ih + 3 hh) in registers for the
// whole kernel. Activations are read with __ldcg (L2 is the coherence point;
// L1 is not coherent across SMs).

#define Bv 128
#define Tv 512
#define Hv 512
#define NCTA 128
#define NTHR 384
#define NTICK (Tv + 2)

__device__ float g_h[3][2][Bv * Hv];      // [layer][parity][b*H + j], zeroed each run
__device__ unsigned g_count = 0;
__device__ unsigned g_phase = 0;

__device__ __forceinline__ void gsync(unsigned target) {
    __syncthreads();
    if (threadIdx.x == 0) {
        __threadfence();                       // publish my writes (L2)
        unsigned a = atomicAdd(&g_count, 1u);
        if (a == NCTA - 1) {
            g_count = 0u;                      // reset for next barrier
            __threadfence();
            atomicAdd(&g_phase, 1u);           // release
        } else {
            while (*((volatile unsigned*)&g_phase) < target) __nanosleep(32);
        }
    }
    __syncthreads();
}

__global__ void __launch_bounds__(NTHR, 1) gru_wavefront(
    const float* __restrict__ x,
    const float* __restrict__ Wih0, const float* __restrict__ Whh0,
    const float* __restrict__ bih0, const float* __restrict__ bhh0,
    const float* __restrict__ Wih1, const float* __restrict__ Whh1,
    const float* __restrict__ bih1, const float* __restrict__ bhh1,
    const float* __restrict__ Wih2, const float* __restrict__ Whh2,
    const float* __restrict__ bih2, const float* __restrict__ bhh2,
    float* __restrict__ y)
{
    const int tid  = threadIdx.x;
    const int w    = tid >> 5;
    const int lane = tid & 31;
    const int unit = blockIdx.x * 12 + w;   // 0..1535
    const int layer = unit >> 9;            // 0,1,2
    const int j     = unit & 511;           // hidden index within layer

    const float* Wih = (layer == 0) ? Wih0 : (layer == 1) ? Wih1 : Wih2;
    const float* Whh = (layer == 0) ? Whh0 : (layer == 1) ? Whh1 : Whh2;
    const float* bihp = (layer == 0) ? bih0 : (layer == 1) ? bih1 : bih2;
    const float* bhhp = (layer == 0) ? bhh0 : (layer == 1) ? bhh1 : bhh2;

    // Register-resident weights: lane owns k in [lane*16, lane*16+16) for
    // gate rows (g*512 + j) of both W_ih and W_hh.  96 floats/thread.
    float4 wi[3][4], wh[3][4];
    float bi[3], bh[3];
#pragma unroll
    for (int g = 0; g < 3; ++g) {
        const float4* pi = (const float4*)(Wih + ((size_t)(g * Hv + j)) * Hv + lane * 16);
        const float4* ph = (const float4*)(Whh + ((size_t)(g * Hv + j)) * Hv + lane * 16);
#pragma unroll
        for (int q = 0; q < 4; ++q) { wi[g][q] = __ldg(pi + q); wh[g][q] = __ldg(ph + q); }
        bi[g] = __ldg(bihp + g * Hv + j);
        bh[g] = __ldg(bhhp + g * Hv + j);
    }

    // Phase base read at entry: graph replays resume from whatever the last
    // run left (monotone counter), so the barrier composes across launches.
    unsigned base = *((volatile unsigned*)&g_phase);

    // Zero hidden-state buffers (initial h = 0 for all layers / parities).
    {
        float* p = (float*)g_h;
        const int total = 3 * 2 * Bv * Hv;
        for (int i = blockIdx.x * NTHR + tid; i < total; i += NCTA * NTHR) p[i] = 0.f;
    }
    gsync(base + 1);

    for (int k = 0; k < NTICK; ++k) {
        const int t  = k - layer;
        const int rp = (k + 1) & 1;   // read parity  (state from tick k-1)
        const int wp = k & 1;         // write parity

        if (t >= 0 && t < Tv) {
            const float* inbase; size_t instride;
            if (layer == 0) { inbase = x + (size_t)t * Hv; instride = (size_t)Tv * Hv; }
            else            { inbase = g_h[layer - 1][rp]; instride = (size_t)Hv; }
            const float* hbase = g_h[layer][rp];
            float*       obase = g_h[layer][wp];

            for (int b = 0; b < Bv; ++b) {
                const float4* ain = (const float4*)(inbase + (size_t)b * instride + lane * 16);
                const float4* ahh = (const float4*)(hbase + (size_t)b * Hv + lane * 16);
                float acc[6] = {0.f, 0.f, 0.f, 0.f, 0.f, 0.f};
#pragma unroll
                for (int q = 0; q < 4; ++q) {
                    float4 a = __ldcg(ain + q);
#pragma unroll
                    for (int g = 0; g < 3; ++g) {
                        acc[g] = fmaf(a.x, wi[g][q].x, acc[g]);
                        acc[g] = fmaf(a.y, wi[g][q].y, acc[g]);
                        acc[g] = fmaf(a.z, wi[g][q].z, acc[g]);
                        acc[g] = fmaf(a.w, wi[g][q].w, acc[g]);
                    }
                }
#pragma unroll
                for (int q = 0; q < 4; ++q) {
                    float4 a = __ldcg(ahh + q);
#pragma unroll
                    for (int g = 0; g < 3; ++g) {
                        acc[3 + g] = fmaf(a.x, wh[g][q].x, acc[3 + g]);
                        acc[3 + g] = fmaf(a.y, wh[g][q].y, acc[3 + g]);
                        acc[3 + g] = fmaf(a.z, wh[g][q].z, acc[3 + g]);
                        acc[3 + g] = fmaf(a.w, wh[g][q].w, acc[3 + g]);
                    }
                }
                // Butterfly reduce the 6 partial dots across the 32 lanes.
#pragma unroll
                for (int off = 16; off; off >>= 1) {
#pragma unroll
                    for (int g = 0; g < 6; ++g)
                        acc[g] += __shfl_xor_sync(0xffffffffu, acc[g], off);
                }
                if (lane == (b & 31)) {   // spread combine work across lanes
                    float r = 1.f / (1.f + expf(-(acc[0] + bi[0] + acc[3] + bh[0])));
                    float z = 1.f / (1.f + expf(-(acc[1] + bi[1] + acc[4] + bh[1])));
                    float n = tanhf(acc[2] + bi[2] + r * (acc[5] + bh[2]));
                    float hp = __ldcg(hbase + (size_t)b * Hv + j);
                    float hv = (1.f - z) * n + z * hp;
                    if (layer == 2) {
                        float xv = __ldg(x + ((size_t)b * Tv + t) * Hv + j);
                        hv = (xv != 0.f) ? hv : 0.f;   // mask; masked value is carried
                        y[((size_t)b * Tv + t) * Hv + j] = hv;
                    }
                    obase[(size_t)b * Hv + j] = hv;
                }
            }
        }
        gsync(base + 2 + k);
    }
}

extern "C" void kernel_launch(void* const* d_in, const int* in_sizes, int n_in,
                              void* d_out, int out_size) {
    (void)in_sizes; (void)n_in; (void)out_size;
    gru_wavefront<<<NCTA, NTHR>>>(
        (const float*)d_in[0],
        (const float*)d_in[1],  (const float*)d_in[2],
        (const float*)d_in[3],  (const float*)d_in[4],
        (const float*)d_in[5],  (const float*)d_in[6],
        (const float*)d_in[7],  (const float*)d_in[8],
        (const float*)d_in[9],  (const float*)d_in[10],
        (const float*)d_in[11], (const float*)d_in[12],
        (float*)d_out);
}

// round 2
// speedup vs baseline: 1.0013x; 1.0013x over previous
#include <cuda_runtime.h>

// 3-layer GRU (PyTorch gate order r,z,n), B=128, T=512, H=512, fp32.
// Persistent wavefront kernel: at tick k, layer l processes timestep t = k - l.
// Double-buffered hidden state (parity = k&1) -> one grid barrier per tick.
// Warp = one hidden unit (1536 units = 128 CTAs x 12 warps); lane holds a
// 16-wide K-slice of all 6 weight rows (3 ih + 3 hh) in registers for the
// whole kernel. Activations are read with __ldcg (L2 is the coherence point;
// L1 is not coherent across SMs).

#define Bv 128
#define Tv 512
#define Hv 512
#define NCTA 128
#define NTHR 384
#define NTICK (Tv + 2)

__device__ float g_h[3][2][Bv * Hv];      // [layer][parity][b*H + j], zeroed each run
__device__ unsigned g_count = 0;
__device__ unsigned g_phase = 0;

__device__ __forceinline__ void gsync(unsigned target) {
    __syncthreads();
    if (threadIdx.x == 0) {
        __threadfence();                       // publish my writes (L2)
        unsigned a = atomicAdd(&g_count, 1u);
        if (a == NCTA - 1) {
            g_count = 0u;                      // reset for next barrier
            __threadfence();
            atomicAdd(&g_phase, 1u);           // release
        } else {
            while (*((volatile unsigned*)&g_phase) < target) __nanosleep(32);
        }
    }
    __syncthreads();
}

__global__ void __launch_bounds__(NTHR, 1) gru_wavefront(
    const float* __restrict__ x,
    const float* __restrict__ Wih0, const float* __restrict__ Whh0,
    const float* __restrict__ bih0, const float* __restrict__ bhh0,
    const float* __restrict__ Wih1, const float* __restrict__ Whh1,
    const float* __restrict__ bih1, const float* __restrict__ bhh1,
    const float* __restrict__ Wih2, const float* __restrict__ Whh2,
    const float* __restrict__ bih2, const float* __restrict__ bhh2,
    float* __restrict__ y)
{
    const int tid  = threadIdx.x;
    const int w    = tid >> 5;
    const int lane = tid & 31;
    const int unit = blockIdx.x * 12 + w;   // 0..1535
    const int layer = unit >> 9;            // 0,1,2
    const int j     = unit & 511;           // hidden index within layer

    const float* Wih = (layer == 0) ? Wih0 : (layer == 1) ? Wih1 : Wih2;
    const float* Whh = (layer == 0) ? Whh0 : (layer == 1) ? Whh1 : Whh2;
    const float* bihp = (layer == 0) ? bih0 : (layer == 1) ? bih1 : bih2;
    const float* bhhp = (layer == 0) ? bhh0 : (layer == 1) ? bhh1 : bhh2;

    // Register-resident weights: lane owns k in [lane*16, lane*16+16) for
    // gate rows (g*512 + j) of both W_ih and W_hh.  96 floats/thread.
    float4 wi[3][4], wh[3][4];
    float bi[3], bh[3];
#pragma unroll
    for (int g = 0; g < 3; ++g) {
        const float4* pi = (const float4*)(Wih + ((size_t)(g * Hv + j)) * Hv + lane * 16);
        const float4* ph = (const float4*)(Whh + ((size_t)(g * Hv + j)) * Hv + lane * 16);
#pragma unroll
        for (int q = 0; q < 4; ++q) { wi[g][q] = __ldg(pi + q); wh[g][q] = __ldg(ph + q); }
        bi[g] = __ldg(bihp + g * Hv + j);
        bh[g] = __ldg(bhhp + g * Hv + j);
    }

    // Phase base read at entry: graph replays resume from whatever the last
    // run left (monotone counter), so the barrier composes across launches.
    unsigned base = *((volatile unsigned*)&g_phase);

    // Zero hidden-state buffers (initial h = 0 for all layers / parities).
    {
        float* p = (float*)g_h;
        const int total = 3 * 2 * Bv * Hv;
        for (int i = blockIdx.x * NTHR + tid; i < total; i += NCTA * NTHR) p[i] = 0.f;
    }
    gsync(base + 1);

    for (int k = 0; k < NTICK; ++k) {
        const int t  = k - layer;
        const int rp = (k + 1) & 1;   // read parity  (state from tick k-1)
        const int wp = k & 1;         // write parity

        if (t >= 0 && t < Tv) {
            const float* inbase; size_t instride;
            if (layer == 0) { inbase = x + (size_t)t * Hv; instride = (size_t)Tv * Hv; }
            else            { inbase = g_h[layer - 1][rp]; instride = (size_t)Hv; }
            const float* hbase = g_h[layer][rp];
            float*       obase = g_h[layer][wp];

            for (int b = 0; b < Bv; ++b) {
                const float4* ain = (const float4*)(inbase + (size_t)b * instride + lane * 16);
                const float4* ahh = (const float4*)(hbase + (size_t)b * Hv + lane * 16);
                float acc[6] = {0.f, 0.f, 0.f, 0.f, 0.f, 0.f};
#pragma unroll
                for (int q = 0; q < 4; ++q) {
                    float4 a = __ldcg(ain + q);
#pragma unroll
                    for (int g = 0; g < 3; ++g) {
                        acc[g] = fmaf(a.x, wi[g][q].x, acc[g]);
                        acc[g] = fmaf(a.y, wi[g][q].y, acc[g]);
                        acc[g] = fmaf(a.z, wi[g][q].z, acc[g]);
                        acc[g] = fmaf(a.w, wi[g][q].w, acc[g]);
                    }
                }
#pragma unroll
                for (int q = 0; q < 4; ++q) {
                    float4 a = __ldcg(ahh + q);
#pragma unroll
                    for (int g = 0; g < 3; ++g) {
                        acc[3 + g] = fmaf(a.x, wh[g][q].x, acc[3 + g]);
                        acc[3 + g] = fmaf(a.y, wh[g][q].y, acc[3 + g]);
                        acc[3 + g] = fmaf(a.z, wh[g][q].z, acc[3 + g]);
                        acc[3 + g] = fmaf(a.w, wh[g][q].w, acc[3 + g]);
                    }
                }
                // Butterfly reduce the 6 partial dots across the 32 lanes.
#pragma unroll
                for (int off = 16; off; off >>= 1) {
#pragma unroll
                    for (int g = 0; g < 6; ++g)
                        acc[g] += __shfl_xor_sync(0xffffffffu, acc[g], off);
                }
                if (lane == (b & 31)) {   // spread combine work across lanes
                    float r = 1.f / (1.f + expf(-(acc[0] + bi[0] + acc[3] + bh[0])));
                    float z = 1.f / (1.f + expf(-(acc[1] + bi[1] + acc[4] + bh[1])));
                    float n = tanhf(acc[2] + bi[2] + r * (acc[5] + bh[2]));
                    float hp = __ldcg(hbase + (size_t)b * Hv + j);
                    float hv = (1.f - z) * n + z * hp;
                    if (layer == 2) {
                        float xv = __ldg(x + ((size_t)b * Tv + t) * Hv + j);
                        hv = (xv != 0.f) ? hv : 0.f;   // mask; masked value is carried
                        y[((size_t)b * Tv + t) * Hv + j] = hv;
                    }
                    obase[(size_t)b * Hv + j] = hv;
                }
            }
        }
        gsync(base + 2 + k);
    }
}

extern "C" void kernel_launch(void* const* d_in, const int* in_sizes, int n_in,
                              void* d_out, int out_size) {
    (void)in_sizes; (void)n_in; (void)out_size;
    gru_wavefront<<<NCTA, NTHR>>>(
        (const float*)d_in[0],
        (const float*)d_in[1],  (const float*)d_in[2],
        (const float*)d_in[3],  (const float*)d_in[4],
        (const float*)d_in[5],  (const float*)d_in[6],
        (const float*)d_in[7],  (const float*)d_in[8],
        (const float*)d_in[9],  (const float*)d_in[10],
        (const float*)d_in[11], (const float*)d_in[12],
        (float*)d_out);
}

// round 3
// speedup vs baseline: 1.1053x; 1.1038x over previous
#include <cuda_runtime.h>
#include <cstdint>

// 3-layer GRU (gate order r,z,n), B=128, T=512, H=512, fp32.
// Persistent wavefront: tick k -> layer l computes t = k - l; double-buffered
// h state (parity k&1), one grid barrier per tick.
// Warp = one hidden unit; weights register-resident (96 f32/thread).
// NEW: activations staged in smem via cp.async.cg (L2-coherent path),
// double-buffered 8-batch chunks, so the 12 warps of a CTA share one copy
// instead of 12 redundant L2 reads.

#define Bv 128
#define Tv 512
#define Hv 512
#define NWARP 12
#define NCTA 128
#define NTHR (NWARP * 32)
#define NTICK (Tv + 2)
#define CHUNK 8
#define NCHUNK (Bv / CHUNK)
#define SLOT_FLOATS (CHUNK * Hv)
#define SMEM_BYTES (2 * 3 * SLOT_FLOATS * 4)

__device__ float g_h[3][2][Bv * Hv];
__device__ unsigned g_count = 0;
__device__ unsigned g_phase = 0;

__device__ __forceinline__ void gsync(unsigned target) {
    __syncthreads();
    if (threadIdx.x == 0) {
        __threadfence();
        unsigned a = atomicAdd(&g_count, 1u);
        if (a == NCTA - 1) {
            g_count = 0u;
            __threadfence();
            atomicAdd(&g_phase, 1u);
        } else {
            while (*((volatile unsigned*)&g_phase) < target) __nanosleep(32);
        }
    }
    __syncthreads();
}

__device__ __forceinline__ void cp16(uint32_t s, const float* g) {
    asm volatile("cp.async.cg.shared.global [%0], [%1], 16;" :: "r"(s), "l"(g));
}
__device__ __forceinline__ void cp_commit() {
    asm volatile("cp.async.commit_group;");
}

__global__ void __launch_bounds__(NTHR, 1) gru_wavefront(
    const float* __restrict__ x,
    const float* __restrict__ Wih0, const float* __restrict__ Whh0,
    const float* __restrict__ bih0, const float* __restrict__ bhh0,
    const float* __restrict__ Wih1, const float* __restrict__ Whh1,
    const float* __restrict__ bih1, const float* __restrict__ bhh1,
    const float* __restrict__ Wih2, const float* __restrict__ Whh2,
    const float* __restrict__ bih2, const float* __restrict__ bhh2,
    float* __restrict__ y)
{
    extern __shared__ float sbuf[];   // [2 parity][3 slots][CHUNK*512]
    const int tid  = threadIdx.x;
    const int w    = tid >> 5;
    const int lane = tid & 31;
    const int unit = blockIdx.x * NWARP + w;   // 0..1535
    const int layer = unit >> 9;               // 0,1,2
    const int j     = unit & 511;

    // Per-CTA layer span (2 CTAs straddle a layer boundary -> 3 sources).
    const int lo = (blockIdx.x * NWARP) >> 9;
    const int hi = (blockIdx.x * NWARP + NWARP - 1) >> 9;
    // slot 0 = input of layer lo; slot 1 = H_lo; slot 2 = H_hi (mixed only)
    const int inSlot = (layer == lo) ? 0 : 1;
    const int hSlot  = (layer == lo) ? 1 : 2;

    const float* Wih = (layer == 0) ? Wih0 : (layer == 1) ? Wih1 : Wih2;
    const float* Whh = (layer == 0) ? Whh0 : (layer == 1) ? Whh1 : Whh2;
    const float* bihp = (layer == 0) ? bih0 : (layer == 1) ? bih1 : bih2;
    const float* bhhp = (layer == 0) ? bhh0 : (layer == 1) ? bhh1 : bhh2;

    // Register-resident weights: lane owns K in [lane*16, lane*16+16) of the
    // 6 gate rows (3 ih + 3 hh).
    float4 wi[3][4], wh[3][4];
    float bi[3], bh[3];
#pragma unroll
    for (int g = 0; g < 3; ++g) {
        const float4* pi = (const float4*)(Wih + ((size_t)(g * Hv + j)) * Hv + lane * 16);
        const float4* ph = (const float4*)(Whh + ((size_t)(g * Hv + j)) * Hv + lane * 16);
#pragma unroll
        for (int q = 0; q < 4; ++q) { wi[g][q] = __ldg(pi + q); wh[g][q] = __ldg(ph + q); }
        bi[g] = __ldg(bihp + g * Hv + j);
        bh[g] = __ldg(bhhp + g * Hv + j);
    }

    unsigned base = *((volatile unsigned*)&g_phase);

    // Zero hidden state (both parities).
    {
        float* p = (float*)g_h;
        const int total = 3 * 2 * Bv * Hv;
        for (int i = blockIdx.x * NTHR + tid; i < total; i += NCTA * NTHR) p[i] = 0.f;
    }
    gsync(base + 1);

    for (int k = 0; k < NTICK; ++k) {
        const int t  = k - layer;
        const bool act = (t >= 0) && (t < Tv);
        const int rp = (k + 1) & 1;
        const int wp = k & 1;

        const int t_lo = k - lo;
        const bool act_lo = (t_lo >= 0) && (t_lo < Tv);
        const int t_hi = k - hi;
        const bool act_hi = (hi > lo) && (t_hi >= 0) && (t_hi < Tv);
        const bool anyAct = act_lo || act_hi;

        if (anyAct) {
            // Source row bases / strides for the <=3 slots.
            const float* s0base; size_t s0str;
            if (lo == 0) { s0base = x + (size_t)t_lo * Hv; s0str = (size_t)Tv * Hv; }
            else         { s0base = g_h[lo - 1][rp];       s0str = (size_t)Hv;      }
            const float* s1base = g_h[lo][rp];
            const float* s2base = g_h[hi][rp];   // only used when hi > lo

            // --- stage one chunk into parity (c&1) ---
            auto stage = [&](int c) {
                const int pb = (c & 1) * 3;
                const int b0 = c * CHUNK;
                if (act_lo) {
                    uint32_t d = (uint32_t)__cvta_generic_to_shared(sbuf + (size_t)(pb + 0) * SLOT_FLOATS);
                    for (int i = tid; i < CHUNK * 128; i += NTHR) {
                        int bl = i >> 7, off = (i & 127) << 2;
                        cp16(d + (((bl << 9) + off) << 2), s0base + (size_t)(b0 + bl) * s0str + off);
                    }
                }
                {
                    uint32_t d = (uint32_t)__cvta_generic_to_shared(sbuf + (size_t)(pb + 1) * SLOT_FLOATS);
                    for (int i = tid; i < CHUNK * 128; i += NTHR) {
                        int bl = i >> 7, off = (i & 127) << 2;
                        cp16(d + (((bl << 9) + off) << 2), s1base + (size_t)((b0 + bl) * Hv) + off);
                    }
                }
                if (act_hi) {
                    uint32_t d = (uint32_t)__cvta_generic_to_shared(sbuf + (size_t)(pb + 2) * SLOT_FLOATS);
                    for (int i = tid; i < CHUNK * 128; i += NTHR) {
                        int bl = i >> 7, off = (i & 127) << 2;
                        cp16(d + (((bl << 9) + off) << 2), s2base + (size_t)((b0 + bl) * Hv) + off);
                    }
                }
                cp_commit();
            };

            stage(0);
            for (int c = 0; c < NCHUNK; ++c) {
                if (c + 1 < NCHUNK) {
                    stage(c + 1);
                    asm volatile("cp.async.wait_group 1;");
                } else {
                    asm volatile("cp.async.wait_group 0;");
                }
                __syncthreads();

                if (act) {
                    const float* inb = sbuf + (size_t)((c & 1) * 3 + inSlot) * SLOT_FLOATS;
                    const float* hb  = sbuf + (size_t)((c & 1) * 3 + hSlot ) * SLOT_FLOATS;
#pragma unroll 1
                    for (int bl = 0; bl < CHUNK; ++bl) {
                        const int b = c * CHUNK + bl;
                        const float4* ain = (const float4*)(inb + bl * Hv + lane * 16);
                        const float4* ahh = (const float4*)(hb  + bl * Hv + lane * 16);
                        float acc[6] = {0.f, 0.f, 0.f, 0.f, 0.f, 0.f};
#pragma unroll
                        for (int q = 0; q < 4; ++q) {
                            float4 a = ain[q];
#pragma unroll
                            for (int g = 0; g < 3; ++g) {
                                acc[g] = fmaf(a.x, wi[g][q].x, acc[g]);
                                acc[g] = fmaf(a.y, wi[g][q].y, acc[g]);
                                acc[g] = fmaf(a.z, wi[g][q].z, acc[g]);
                                acc[g] = fmaf(a.w, wi[g][q].w, acc[g]);
                            }
                        }
#pragma unroll
                        for (int q = 0; q < 4; ++q) {
                            float4 a = ahh[q];
#pragma unroll
                            for (int g = 0; g < 3; ++g) {
                                acc[3 + g] = fmaf(a.x, wh[g][q].x, acc[3 + g]);
                                acc[3 + g] = fmaf(a.y, wh[g][q].y, acc[3 + g]);
                                acc[3 + g] = fmaf(a.z, wh[g][q].z, acc[3 + g]);
                                acc[3 + g] = fmaf(a.w, wh[g][q].w, acc[3 + g]);
                            }
                        }
#pragma unroll
                        for (int off = 16; off; off >>= 1) {
#pragma unroll
                            for (int g = 0; g < 6; ++g)
                                acc[g] += __shfl_xor_sync(0xffffffffu, acc[g], off);
                        }
                        if (lane == (b & 31)) {
                            float r = 1.f / (1.f + __expf(-(acc[0] + bi[0] + acc[3] + bh[0])));
                            float z = 1.f / (1.f + __expf(-(acc[1] + bi[1] + acc[4] + bh[1])));
                            float n = tanhf(acc[2] + bi[2] + r * (acc[5] + bh[2]));
                            float hp = hb[bl * Hv + j];
                            float hv = (1.f - z) * n + z * hp;
                            if (layer == 2) {
                                float xv = __ldg(x + ((size_t)b * Tv + t) * Hv + j);
                                hv = (xv != 0.f) ? hv : 0.f;
                                y[((size_t)b * Tv + t) * Hv + j] = hv;
                            }
                            g_h[layer][wp][(size_t)b * Hv + j] = hv;
                        }
                    }
                }
                __syncthreads();
            }
        }
        gsync(base + 2 + k);
    }
}

extern "C" void kernel_launch(void* const* d_in, const int* in_sizes, int n_in,
                              void* d_out, int out_size) {
    (void)in_sizes; (void)n_in; (void)out_size;
    cudaFuncSetAttribute(gru_wavefront,
                         cudaFuncAttributeMaxDynamicSharedMemorySize, SMEM_BYTES);
    gru_wavefront<<<NCTA, NTHR, SMEM_BYTES>>>(
        (const float*)d_in[0],
        (const float*)d_in[1],  (const float*)d_in[2],
        (const float*)d_in[3],  (const float*)d_in[4],
        (const float*)d_in[5],  (const float*)d_in[6],
        (const float*)d_in[7],  (const float*)d_in[8],
        (const float*)d_in[9],  (const float*)d_in[10],
        (const float*)d_in[11], (const float*)d_in[12],
        (float*)d_out);
}